// round 9
// baseline (speedup 1.0000x reference)
#include <cuda_runtime.h>
#include <cuda_bf16.h>

// AttentionAggregator: out[n] = softmax_k(feats[n,k]·w) weighted sum of feats[n,k]
// feats[n,k] = embed_table[neigh_idx[n,k]]  (gather, D=128, K=10)
//
// R9: TWO warps per node (each owns 64 dims, float2/lane). Halves the feat
// register payload (40->20 regs) -> regs capped 51 -> 40 warps/SM (62.5% occ
// vs 50% cap before). R3-R8 showed no unit saturated (DRAM~51/L1~64/issue~51)
// with dur invariant to instruction shape => latency-bound at 32-warp cap;
// more warps in flight is the remaining lever.
// Scores: per-warp butterfly partial + smem cross-warp combine (1 barrier).
// Gather: __ldcg (L2-only). Output: __stcs streaming.

#define K_NEIGH 10
#define D_DIM   128

__global__ __launch_bounds__(256, 5) void attn_agg_kernel(
    const float* __restrict__ table,   // [VOCAB, 128]
    const float* __restrict__ attn_w,  // [128]
    const int*  __restrict__ nidx,     // [N, 10] (int32)
    float* __restrict__ out,           // [N, 128]
    int n_nodes)
{
    __shared__ float partial[8][K_NEIGH];   // per-warp score partials

    int tid  = threadIdx.x;
    int wid  = tid >> 5;          // 0..7
    int lane = tid & 31;
    int slot = wid >> 1;          // node slot within block: 0..3
    int half = wid & 1;           // which 64-dim half of the row

    long long node = (long long)blockIdx.x * 4 + slot;
    if (node >= n_nodes) node = n_nodes - 1;   // barrier-safe clamp (dup write is identical bytes)

    // attn_w slice: this warp's half, this lane's 2 dims
    const float2 w2 = __ldg(reinterpret_cast<const float2*>(attn_w + half * 64) + lane);

    const int* ni = nidx + node * K_NEIGH;

    float2 f[K_NEIGH];
    float  s[K_NEIGH];

    // Gather: each warp loads a contiguous 256B half-row per neighbor (MLP=10).
    #pragma unroll
    for (int k = 0; k < K_NEIGH; k++) {
        long long row = (long long)__ldg(ni + k);   // uniform broadcast
        f[k] = __ldcg(reinterpret_cast<const float2*>(table + row * D_DIM + half * 64) + lane);
    }

    // Per-warp partial scores over this 64-dim half
    #pragma unroll
    for (int k = 0; k < K_NEIGH; k++) {
        float p = f[k].x * w2.x + f[k].y * w2.y;
        p += __shfl_xor_sync(0xffffffffu, p, 16);
        p += __shfl_xor_sync(0xffffffffu, p, 8);
        p += __shfl_xor_sync(0xffffffffu, p, 4);
        p += __shfl_xor_sync(0xffffffffu, p, 2);
        p += __shfl_xor_sync(0xffffffffu, p, 1);
        s[k] = p;
        if (lane == 0) partial[wid][k] = p;
    }
    __syncthreads();

    // Add peer warp's partial -> full scores (identical in both warps)
    #pragma unroll
    for (int k = 0; k < K_NEIGH; k++) s[k] += partial[wid ^ 1][k];

    // softmax over K in registers
    float m = s[0];
    #pragma unroll
    for (int k = 1; k < K_NEIGH; k++) m = fmaxf(m, s[k]);
    float sum = 0.0f;
    #pragma unroll
    for (int k = 0; k < K_NEIGH; k++) { s[k] = __expf(s[k] - m); sum += s[k]; }
    float inv = __frcp_rn(sum);

    // weighted sum of register-resident half-row feats
    float2 acc = make_float2(0.f, 0.f);
    #pragma unroll
    for (int k = 0; k < K_NEIGH; k++) {
        float wk = s[k] * inv;
        acc.x = fmaf(wk, f[k].x, acc.x);
        acc.y = fmaf(wk, f[k].y, acc.y);
    }

    // Streaming store of this warp's 64-dim half
    __stcs(reinterpret_cast<float2*>(out + node * D_DIM + half * 64) + lane, acc);
}

extern "C" void kernel_launch(void* const* d_in, const int* in_sizes, int n_in,
                              void* d_out, int out_size)
{
    const float* table  = (const float*)d_in[0];  // [VOCAB*128]
    const float* attn_w = (const float*)d_in[1];  // [128]
    const int*   nidx   = (const int*)d_in[2];    // [N*10] int32

    int n_nodes = in_sizes[2] / K_NEIGH;
    float* out = (float*)d_out;

    const int threads = 256;                  // 8 warps -> 4 nodes per block
    int blocks = (n_nodes + 3) / 4;
    attn_agg_kernel<<<blocks, threads>>>(table, attn_w, nidx, out, n_nodes);
}

// round 10
// speedup vs baseline: 1.6137x; 1.6137x over previous
#include <cuda_runtime.h>
#include <cuda_bf16.h>

// AttentionAggregator: out[n] = softmax_k(feats[n,k]·w) weighted sum of feats[n,k]
// feats[n,k] = embed_table[neigh_idx[n,k]]  (gather, D=128, K=10)
//
// R10: one warp per node (R3 skeleton — proven minimal-work shape), but ONLINE
// softmax over 2 chunks of 5 neighbors. Register payload halves (f[10]->f[5]
// float4: 40->20 regs) -> regs<=51 -> 40 warps/SM (62.5% occ vs 50% cap),
// with ZERO added memory instructions (R9's mistake). +2 exp / +10 FMA rescale.

#define K_NEIGH 10
#define KC      5       // chunk size
#define D_DIM   128

__global__ __launch_bounds__(256, 5) void attn_agg_kernel(
    const float* __restrict__ table,   // [VOCAB, 128]
    const float* __restrict__ attn_w,  // [128]
    const int*  __restrict__ nidx,     // [N, 10] (int32)
    float* __restrict__ out,           // [N, 128]
    int n_nodes)
{
    int warp = (int)((blockIdx.x * (unsigned)blockDim.x + threadIdx.x) >> 5);
    int lane = threadIdx.x & 31;
    if (warp >= n_nodes) return;

    // attn_w slice for this lane's 4 dims
    const float4 w4 = __ldg(reinterpret_cast<const float4*>(attn_w) + lane);

    const int* ni = nidx + (long long)warp * K_NEIGH;

    // online-softmax running state
    float m_run = -1e30f;
    float d_run = 0.0f;
    float4 acc = make_float4(0.f, 0.f, 0.f, 0.f);

    #pragma unroll
    for (int c = 0; c < K_NEIGH / KC; c++) {
        float4 f[KC];
        float  s[KC];

        // Gather chunk: 5 independent row loads (L2-only), coalesced 512B rows.
        #pragma unroll
        for (int k = 0; k < KC; k++) {
            long long row = (long long)__ldg(ni + c * KC + k);  // uniform broadcast
            f[k] = __ldcg(reinterpret_cast<const float4*>(table + row * D_DIM) + lane);
        }

        // Scores for chunk (full-warp butterfly -> every lane has s[k])
        #pragma unroll
        for (int k = 0; k < KC; k++) {
            float p = f[k].x * w4.x + f[k].y * w4.y + f[k].z * w4.z + f[k].w * w4.w;
            p += __shfl_xor_sync(0xffffffffu, p, 16);
            p += __shfl_xor_sync(0xffffffffu, p, 8);
            p += __shfl_xor_sync(0xffffffffu, p, 4);
            p += __shfl_xor_sync(0xffffffffu, p, 2);
            p += __shfl_xor_sync(0xffffffffu, p, 1);
            s[k] = p;
        }

        // Online softmax update
        float m_new = m_run;
        #pragma unroll
        for (int k = 0; k < KC; k++) m_new = fmaxf(m_new, s[k]);

        float scale = __expf(m_run - m_new);
        d_run *= scale;
        acc.x *= scale; acc.y *= scale; acc.z *= scale; acc.w *= scale;

        #pragma unroll
        for (int k = 0; k < KC; k++) {
            float e = __expf(s[k] - m_new);
            d_run += e;
            acc.x = fmaf(e, f[k].x, acc.x);
            acc.y = fmaf(e, f[k].y, acc.y);
            acc.z = fmaf(e, f[k].z, acc.z);
            acc.w = fmaf(e, f[k].w, acc.w);
        }
        m_run = m_new;
    }

    float inv = __frcp_rn(d_run);
    acc.x *= inv; acc.y *= inv; acc.z *= inv; acc.w *= inv;

    // Streaming store: write-once output, keep table resident in L2.
    __stcs(reinterpret_cast<float4*>(out + (long long)warp * D_DIM) + lane, acc);
}

extern "C" void kernel_launch(void* const* d_in, const int* in_sizes, int n_in,
                              void* d_out, int out_size)
{
    const float* table  = (const float*)d_in[0];  // [VOCAB*128]
    const float* attn_w = (const float*)d_in[1];  // [128]
    const int*   nidx   = (const int*)d_in[2];    // [N*10] int32

    int n_nodes = in_sizes[2] / K_NEIGH;
    float* out = (float*)d_out;

    const int threads = 256;               // 8 warps -> 8 nodes per block
    int blocks = (n_nodes + 7) / 8;
    attn_agg_kernel<<<blocks, threads>>>(table, attn_w, nidx, out, n_nodes);
}